// round 12
// baseline (speedup 1.0000x reference)
#include <cuda_runtime.h>

#define NPTS     200000
#define NREL     128
#define SCT_PTS  1352        // ceil(200000/148): exactly 148 scatter windows
#define NBLK     ((NPTS + SCT_PTS - 1) / SCT_PTS)   // 148 = one CTA per SM
#define CELLCAP  32          // per-(relation, window) capacity; mean 10.6, sd 3.2
#define CTAS_PER_REL 6
#define GRID_MAIN (NREL * CTAS_PER_REL)   // 768: UNIFORM CTAs per relation
#define THREADS  256
#define WSTRIDE  36          // words per lane in smem weight tile (bank swizzle)

// ---- device scratch (no allocations). Everything below is rewritten by
//      k_scatter each launch (or never consumed past the written count). ----
__device__ int g_cellcnt[NREL * NBLK];
__device__ int g_cursor[NREL];
__device__ int g_pids[NREL * NBLK * CELLCAP];

// Scatter: window blk (one CTA per SM) bins its 1352 points into its OWN
// fixed cell per relation (plain stores, no global atomics). Block 0
// rezeroes the work-stealing cursors. Overflow beyond CELLCAP (>6.6 sigma)
// computed inline.
__global__ void __launch_bounds__(256)
k_scatter(const int* __restrict__ rel, int n,
          const float* __restrict__ x,
          const float* __restrict__ w,
          float* __restrict__ out) {
    __shared__ int s_rel[SCT_PTS];
    __shared__ int s_hist[NREL];
    __shared__ int s_cur[NREL];

    int blk = blockIdx.x;
    if (blk == 0) {
        for (int i = threadIdx.x; i < NREL; i += blockDim.x) g_cursor[i] = 0;
    }

    int start = blk * SCT_PTS;
    int cnt = n - start;
    if (cnt > SCT_PTS) cnt = SCT_PTS;

    for (int i = threadIdx.x; i < NREL; i += blockDim.x) {
        s_hist[i] = 0;
        s_cur[i]  = 0;
    }
    __syncthreads();

    for (int i = threadIdx.x; i < cnt; i += blockDim.x) {
        int r = __ldg(rel + start + i);
        s_rel[i] = r;
        atomicAdd(&s_hist[r], 1);
    }
    __syncthreads();

    for (int i = threadIdx.x; i < NREL; i += blockDim.x) {
        int c = s_hist[i];
        g_cellcnt[i * NBLK + blk] = (c > CELLCAP) ? CELLCAP : c;
    }
    __syncthreads();

    for (int i = threadIdx.x; i < cnt; i += blockDim.x) {
        int r = s_rel[i];
        int pos = atomicAdd(&s_cur[r], 1);
        int p = start + i;
        if (pos < CELLCAP) {
            g_pids[(r * NBLK + blk) * CELLCAP + pos] = p;
        } else {
            // Dead-in-practice overflow: compute this point directly.
            const float* xr = x + (size_t)p * 128;
            float* orow = out + (size_t)p * 128;
            for (int bb = 0; bb < 16; bb++) {
                const float* wb = w + (size_t)((r * 16 + bb) * 8) * 8;
                for (int o = 0; o < 8; o++) {
                    float acc = 0.f;
                    for (int ii = 0; ii < 8; ii++)
                        acc = fmaf(xr[bb * 8 + ii], wb[ii * 8 + o], acc);
                    orow[bb * 8 + o] = acc;
                }
            }
        }
    }

    __syncthreads();
#if __CUDA_ARCH__ >= 900
    cudaTriggerProgrammaticLaunchCompletion();
#endif
}

// Main: 768 CTAs (UNIFORM 6 per relation — R11 showed uneven CTA counts
// create a 12% tail), 8 warps/CTA = 48 warps/relation, regs<=42, ~5.2
// CTAs/SM. Relation's 4KB weight tile in bank-swizzled SHARED MEMORY
// (lane stride 36 words, conflict-free LDS.128). lane=2b+h owns block b,
// out-half h. Batch-2 fused inner loop (one weight LDS per 2 points).
// KEY CHANGE vs R10: PAIR-STEALING — atomicAdd(cursor, 2) grabs TWO
// adjacent ~10.6-pt cells per steal (~950cy of work >= the ~900cy
// steal->meta chain), so depth-1 prefetch of the next PAIR fully covers
// the chain, and steal atomics are halved.
__global__ void __launch_bounds__(THREADS, 6)
k_main(const float4* __restrict__ x4,
       const float4* __restrict__ w4,
       float4* __restrict__ out4,
       int ncell) {
    __shared__ float s_w[32 * WSTRIDE];   // 4608 B

    int r    = blockIdx.x % NREL;
    int tid  = threadIdx.x;
    int lane = tid & 31;
    int b    = lane >> 1;

    // ---- independent preamble (PDL): stage weights ----
    {
        int l  = tid >> 3;
        int i  = tid & 7;
        int bb = l >> 1;
        int hh = l & 1;
        float4 w = __ldg(w4 + (size_t)((r * 16 + bb) * 8 + i) * 2 + hh);
        *(float4*)(s_w + l * WSTRIDE + i * 4) = w;
    }

#if __CUDA_ARCH__ >= 900
    cudaGridDependencySynchronize();
#endif
    __syncthreads();

    const float4* wl = (const float4*)(s_w + lane * WSTRIDE);  // wl[i], i<8

#define STEAL2(BASE)                                                 \
    {                                                                \
        int t = 0;                                                   \
        if (lane == 0) t = atomicAdd(&g_cursor[r], 2);               \
        (BASE) = __shfl_sync(0xffffffffu, t, 0);                     \
    }

#define LOADCELL(C, CNT, PID)                                        \
    {                                                                \
        (CNT) = 0; (PID) = 0;                                        \
        if ((C) < ncell) {                                           \
            int ci = r * NBLK + (C);                                 \
            (CNT) = __ldg(&g_cellcnt[ci]);                           \
            (PID) = __ldg(g_pids + (size_t)ci * CELLCAP + lane);     \
        }                                                            \
    }

// Process one cell (fused batch-2: one weight LDS per two points).
#define PROCESS_CELL(CNT, PID)                                               \
    {                                                                        \
        int k = 0;                                                           \
        for (; k + 2 <= (CNT); k += 2) {                                     \
            int p0 = __shfl_sync(0xffffffffu, (PID), k);                     \
            int p1 = __shfl_sync(0xffffffffu, (PID), k + 1);                 \
            float4 xa0 = __ldg(x4 + (size_t)p0 * 32 + 2 * b);                \
            float4 xb0 = __ldg(x4 + (size_t)p0 * 32 + 2 * b + 1);            \
            float4 xa1 = __ldg(x4 + (size_t)p1 * 32 + 2 * b);                \
            float4 xb1 = __ldg(x4 + (size_t)p1 * 32 + 2 * b + 1);            \
            float xs0[8] = {xa0.x, xa0.y, xa0.z, xa0.w,                      \
                            xb0.x, xb0.y, xb0.z, xb0.w};                     \
            float xs1[8] = {xa1.x, xa1.y, xa1.z, xa1.w,                      \
                            xb1.x, xb1.y, xb1.z, xb1.w};                     \
            float u0 = 0.f, u1 = 0.f, u2 = 0.f, u3 = 0.f;                    \
            float v0 = 0.f, v1 = 0.f, v2 = 0.f, v3 = 0.f;                    \
            _Pragma("unroll")                                                \
            for (int i = 0; i < 8; i++) {                                    \
                float4 w = wl[i];                                            \
                u0 = fmaf(xs0[i], w.x, u0);                                  \
                u1 = fmaf(xs0[i], w.y, u1);                                  \
                u2 = fmaf(xs0[i], w.z, u2);                                  \
                u3 = fmaf(xs0[i], w.w, u3);                                  \
                v0 = fmaf(xs1[i], w.x, v0);                                  \
                v1 = fmaf(xs1[i], w.y, v1);                                  \
                v2 = fmaf(xs1[i], w.z, v2);                                  \
                v3 = fmaf(xs1[i], w.w, v3);                                  \
            }                                                                \
            out4[(size_t)p0 * 32 + lane] = make_float4(u0, u1, u2, u3);      \
            out4[(size_t)p1 * 32 + lane] = make_float4(v0, v1, v2, v3);      \
        }                                                                    \
        if (k < (CNT)) {                                                     \
            int p = __shfl_sync(0xffffffffu, (PID), k);                      \
            float4 xa = __ldg(x4 + (size_t)p * 32 + 2 * b);                  \
            float4 xb = __ldg(x4 + (size_t)p * 32 + 2 * b + 1);              \
            float xs[8] = {xa.x, xa.y, xa.z, xa.w,                           \
                           xb.x, xb.y, xb.z, xb.w};                          \
            float u0 = 0.f, u1 = 0.f, u2 = 0.f, u3 = 0.f;                    \
            _Pragma("unroll")                                                \
            for (int i = 0; i < 8; i++) {                                    \
                float4 w = wl[i];                                            \
                u0 = fmaf(xs[i], w.x, u0);                                   \
                u1 = fmaf(xs[i], w.y, u1);                                   \
                u2 = fmaf(xs[i], w.z, u2);                                   \
                u3 = fmaf(xs[i], w.w, u3);                                   \
            }                                                                \
            out4[(size_t)p * 32 + lane] = make_float4(u0, u1, u2, u3);       \
        }                                                                    \
    }

    // pair A (processing) / pair B (in flight)
    int baseA, baseB;
    int cnt0A, pid0A, cnt1A, pid1A;
    int cnt0B, pid0B, cnt1B, pid1B;

    STEAL2(baseA)
    LOADCELL(baseA,     cnt0A, pid0A)
    LOADCELL(baseA + 1, cnt1A, pid1A)

    while (baseA < ncell) {
        // depth-1 prefetch of the NEXT pair (covers the steal->meta chain)
        STEAL2(baseB)
        LOADCELL(baseB,     cnt0B, pid0B)
        LOADCELL(baseB + 1, cnt1B, pid1B)

        PROCESS_CELL(cnt0A, pid0A)
        PROCESS_CELL(cnt1A, pid1A)

        baseA = baseB;
        cnt0A = cnt0B; pid0A = pid0B;
        cnt1A = cnt1B; pid1A = pid1B;
    }
#undef PROCESS_CELL
#undef LOADCELL
#undef STEAL2
}

extern "C" void kernel_launch(void* const* d_in, const int* in_sizes, int n_in,
                              void* d_out, int out_size) {
    const float* x      = (const float*)d_in[0];   // [NPTS, 128] f32
    const float* blocks = (const float*)d_in[1];   // [128,16,8,8] f32
    const int*   rel    = (const int*)d_in[2];     // [NPTS] i32
    int n = in_sizes[2];
    if (n > NPTS) n = NPTS;  // scratch bound

    int nblk = (n + SCT_PTS - 1) / SCT_PTS;        // 148

    k_scatter<<<nblk, 256>>>(rel, n, x, blocks, (float*)d_out);

    // k_main with PDL: launches early, stages weights, grid-dependency-
    // syncs before reading scatter outputs.
    cudaLaunchConfig_t cfg = {};
    cfg.gridDim  = dim3(GRID_MAIN);
    cfg.blockDim = dim3(THREADS);
    cfg.dynamicSmemBytes = 0;
    cfg.stream   = 0;
    cudaLaunchAttribute attr[1];
    attr[0].id = cudaLaunchAttributeProgrammaticStreamSerialization;
    attr[0].val.programmaticStreamSerializationAllowed = 1;
    cfg.attrs    = attr;
    cfg.numAttrs = 1;
    cudaLaunchKernelEx(&cfg, k_main,
                       (const float4*)x, (const float4*)blocks,
                       (float4*)d_out, nblk);
}

// round 13
// speedup vs baseline: 1.0860x; 1.0860x over previous
#include <cuda_runtime.h>

#define NPTS     200000
#define NREL     128
#define SCT_PTS  1024
#define NBLK     ((NPTS + SCT_PTS - 1) / SCT_PTS)   // 196
#define CELLCAP  32          // per-(relation, window) capacity; mean 8, sd 2.8
#define CTAS_PER_REL 6
#define GRID_MAIN (NREL * CTAS_PER_REL)   // 768, uniform 6 CTAs/relation
#define THREADS  256
#define WSTRIDE  36          // words per lane in smem weight tile (bank swizzle)

// ---- device scratch (no allocations). Everything below is rewritten by
//      k_scatter each launch (or never consumed past the written count). ----
__device__ int g_cellcnt[NREL * NBLK];
__device__ int g_cursor[NREL];
__device__ int g_pids[NREL * NBLK * CELLCAP];

// Scatter (SINGLE PASS): window blk bins its 1024 points into its OWN fixed
// cell per relation. pos comes straight from the smem cursor atomic; the
// per-window cell counts are published AFTER the pass from s_cur (so no
// histogram pre-pass, no s_rel staging, 2 fewer __syncthreads). Block 0
// rezeroes the work-stealing cursors. Overflow beyond CELLCAP (>8 sigma)
// computed inline.
__global__ void __launch_bounds__(256)
k_scatter(const int* __restrict__ rel, int n,
          const float* __restrict__ x,
          const float* __restrict__ w,
          float* __restrict__ out) {
    __shared__ int s_cur[NREL];

    int blk = blockIdx.x;
    if (blk == 0) {
        for (int i = threadIdx.x; i < NREL; i += blockDim.x) g_cursor[i] = 0;
    }

    int start = blk * SCT_PTS;
    int cnt = n - start;
    if (cnt > SCT_PTS) cnt = SCT_PTS;

    for (int i = threadIdx.x; i < NREL; i += blockDim.x) s_cur[i] = 0;
    __syncthreads();

    for (int i = threadIdx.x; i < cnt; i += blockDim.x) {
        int r = __ldg(rel + start + i);
        int pos = atomicAdd(&s_cur[r], 1);
        int p = start + i;
        if (pos < CELLCAP) {
            g_pids[(r * NBLK + blk) * CELLCAP + pos] = p;
        } else {
            // Dead-in-practice overflow: compute this point directly.
            const float* xr = x + (size_t)p * 128;
            float* orow = out + (size_t)p * 128;
            for (int bb = 0; bb < 16; bb++) {
                const float* wb = w + (size_t)((r * 16 + bb) * 8) * 8;
                for (int o = 0; o < 8; o++) {
                    float acc = 0.f;
                    for (int ii = 0; ii < 8; ii++)
                        acc = fmaf(xr[bb * 8 + ii], wb[ii * 8 + o], acc);
                    orow[bb * 8 + o] = acc;
                }
            }
        }
    }
    __syncthreads();

    for (int i = threadIdx.x; i < NREL; i += blockDim.x) {
        int c = s_cur[i];
        g_cellcnt[i * NBLK + blk] = (c > CELLCAP) ? CELLCAP : c;
    }

    __syncthreads();
#if __CUDA_ARCH__ >= 900
    cudaTriggerProgrammaticLaunchCompletion();
#endif
}

// Main — EXACT R10 winner (39.0us, confirmed twice; R11/R12 scheduling
// perturbations all regressed): CTA = one relation, 8 warps/CTA, 6
// CTAs/relation = 48 warps/relation, single wave, regs<=42. Relation's
// 4KB weight tile in bank-swizzled SHARED MEMORY (lane stride 36 words,
// conflict-free LDS.128). lane = 2b+h owns block b, out-half h. Batch-2
// fused inner loop: each weight float4 LDS'd once, applied to both points.
// Work-stealing of single ~8-pt cells with depth-1 prefetch (4.08
// cells/warp — the granularity that balanced best).
__global__ void __launch_bounds__(THREADS, 6)
k_main(const float4* __restrict__ x4,
       const float4* __restrict__ w4,
       float4* __restrict__ out4,
       int ncell) {
    __shared__ float s_w[32 * WSTRIDE];   // 4608 B

    int r    = blockIdx.x % NREL;
    int tid  = threadIdx.x;
    int lane = tid & 31;
    int b    = lane >> 1;

    // ---- independent preamble (PDL): stage weights ----
    {
        int l  = tid >> 3;
        int i  = tid & 7;
        int bb = l >> 1;
        int hh = l & 1;
        float4 w = __ldg(w4 + (size_t)((r * 16 + bb) * 8 + i) * 2 + hh);
        *(float4*)(s_w + l * WSTRIDE + i * 4) = w;
    }

#if __CUDA_ARCH__ >= 900
    cudaGridDependencySynchronize();
#endif
    __syncthreads();

    const float4* wl = (const float4*)(s_w + lane * WSTRIDE);  // wl[i], i<8

#define STEAL(C)                                                     \
    {                                                                \
        int t = 0;                                                   \
        if (lane == 0) t = atomicAdd(&g_cursor[r], 1);               \
        (C) = __shfl_sync(0xffffffffu, t, 0);                        \
    }

    int cA;
    STEAL(cA)
    int cntA = 0, pidA = 0;
    if (cA < ncell) {
        int ci = r * NBLK + cA;
        cntA = __ldg(&g_cellcnt[ci]);
        pidA = __ldg(g_pids + (size_t)ci * CELLCAP + lane);
    }

    while (cA < ncell) {
        // prefetch next cell while processing this one
        int cB;
        STEAL(cB)
        int cntB = 0, pidB = 0;
        if (cB < ncell) {
            int ci = r * NBLK + cB;
            cntB = __ldg(&g_cellcnt[ci]);
            pidB = __ldg(g_pids + (size_t)ci * CELLCAP + lane);
        }

        int k = 0;
        for (; k + 2 <= cntA; k += 2) {
            int p0 = __shfl_sync(0xffffffffu, pidA, k);
            int p1 = __shfl_sync(0xffffffffu, pidA, k + 1);
            float4 xa0 = __ldg(x4 + (size_t)p0 * 32 + 2 * b);
            float4 xb0 = __ldg(x4 + (size_t)p0 * 32 + 2 * b + 1);
            float4 xa1 = __ldg(x4 + (size_t)p1 * 32 + 2 * b);
            float4 xb1 = __ldg(x4 + (size_t)p1 * 32 + 2 * b + 1);

            float xs0[8] = {xa0.x, xa0.y, xa0.z, xa0.w,
                            xb0.x, xb0.y, xb0.z, xb0.w};
            float xs1[8] = {xa1.x, xa1.y, xa1.z, xa1.w,
                            xb1.x, xb1.y, xb1.z, xb1.w};
            float u0 = 0.f, u1 = 0.f, u2 = 0.f, u3 = 0.f;
            float v0 = 0.f, v1 = 0.f, v2 = 0.f, v3 = 0.f;
#pragma unroll
            for (int i = 0; i < 8; i++) {
                float4 w = wl[i];             // ONE LDS, used by BOTH points
                u0 = fmaf(xs0[i], w.x, u0);
                u1 = fmaf(xs0[i], w.y, u1);
                u2 = fmaf(xs0[i], w.z, u2);
                u3 = fmaf(xs0[i], w.w, u3);
                v0 = fmaf(xs1[i], w.x, v0);
                v1 = fmaf(xs1[i], w.y, v1);
                v2 = fmaf(xs1[i], w.z, v2);
                v3 = fmaf(xs1[i], w.w, v3);
            }
            out4[(size_t)p0 * 32 + lane] = make_float4(u0, u1, u2, u3);
            out4[(size_t)p1 * 32 + lane] = make_float4(v0, v1, v2, v3);
        }
        if (k < cntA) {
            int p = __shfl_sync(0xffffffffu, pidA, k);
            float4 xa = __ldg(x4 + (size_t)p * 32 + 2 * b);
            float4 xb = __ldg(x4 + (size_t)p * 32 + 2 * b + 1);
            float xs[8] = {xa.x, xa.y, xa.z, xa.w, xb.x, xb.y, xb.z, xb.w};
            float u0 = 0.f, u1 = 0.f, u2 = 0.f, u3 = 0.f;
#pragma unroll
            for (int i = 0; i < 8; i++) {
                float4 w = wl[i];
                u0 = fmaf(xs[i], w.x, u0);
                u1 = fmaf(xs[i], w.y, u1);
                u2 = fmaf(xs[i], w.z, u2);
                u3 = fmaf(xs[i], w.w, u3);
            }
            out4[(size_t)p * 32 + lane] = make_float4(u0, u1, u2, u3);
        }

        cA = cB; cntA = cntB; pidA = pidB;
    }
#undef STEAL
}

extern "C" void kernel_launch(void* const* d_in, const int* in_sizes, int n_in,
                              void* d_out, int out_size) {
    const float* x      = (const float*)d_in[0];   // [NPTS, 128] f32
    const float* blocks = (const float*)d_in[1];   // [128,16,8,8] f32
    const int*   rel    = (const int*)d_in[2];     // [NPTS] i32
    int n = in_sizes[2];
    if (n > NPTS) n = NPTS;  // scratch bound

    int nblk = (n + SCT_PTS - 1) / SCT_PTS;        // 196

    k_scatter<<<nblk, 256>>>(rel, n, x, blocks, (float*)d_out);

    // k_main with PDL: launches early, stages weights, grid-dependency-
    // syncs before reading scatter outputs.
    cudaLaunchConfig_t cfg = {};
    cfg.gridDim  = dim3(GRID_MAIN);
    cfg.blockDim = dim3(THREADS);
    cfg.dynamicSmemBytes = 0;
    cfg.stream   = 0;
    cudaLaunchAttribute attr[1];
    attr[0].id = cudaLaunchAttributeProgrammaticStreamSerialization;
    attr[0].val.programmaticStreamSerializationAllowed = 1;
    cfg.attrs    = attr;
    cfg.numAttrs = 1;
    cudaLaunchKernelEx(&cfg, k_main,
                       (const float4*)x, (const float4*)blocks,
                       (float4*)d_out, nblk);
}